// round 17
// baseline (speedup 1.0000x reference)
#include <cuda_runtime.h>
#include <cstdint>

#define LMAX  6
#define BATCH 1024
#define F     64
#define IR    455
#define NROT  64
#define FS    (F * IR)   // 29120 floats per batch element

// Raw packed pre-scaled weights W_l[k, n] (f32), k=(f*d+u), n=(g*d+v).
__device__ float g_W[4096 * 455];
// Fragment-ordered s8 limb planes of W (per l base 2048*off[l] u32):
//   per (kc32, bn) tile: 1024 u32 = [limb hi 512 | limb lo 512],
//   widx = wt*256 + half*128 + lane*4 + j ; j -> (ni = 2*half + (j>>1), reg = j&1)
__device__ uint32_t g_Wq[2048 * 455];
// Per-column quantization factor and epilogue scale (3136 columns total).
__device__ float g_qf[3136];
__device__ float g_epi[3136];   // = 128 * colmax / (16300 * 2048)

// Tile decode tables, ordered l = 6..0 (largest K first).
__constant__ int c_cnt[7]  = {1352, 968, 648, 392, 200, 72, 8}; // 8*d*d
__constant__ int c_d[7]    = {13, 11, 9, 7, 5, 3, 1};
__constant__ int c_off[7]  = {286, 165, 84, 35, 10, 1, 0};
__constant__ int c_colb[7] = {2304, 1600, 1024, 576, 256, 64, 0};

// ---------------------------------------------------------------------------
// helpers
// ---------------------------------------------------------------------------
__device__ __forceinline__ uint32_t pack4b(int b0, int b1, int b2, int b3) {
    return (uint32_t)(b0 & 255) | ((uint32_t)(b1 & 255) << 8)
         | ((uint32_t)(b2 & 255) << 16) | ((uint32_t)(b3 & 255) << 24);
}

// quantize 4 floats (scale 2048) -> hi-limb word, lo-limb word
__device__ __forceinline__ void quant4(const float* f, uint32_t& hw, uint32_t& lw) {
    int h[4], lo[4];
#pragma unroll
    for (int i = 0; i < 4; ++i) {
        int qv = __float2int_rn(f[i] * 2048.0f);
        int tt = qv + 16448;           // + 16384 + 64 (rounding split bias)
        int hb = tt >> 7;
        lo[i]  = tt - 64 - (hb << 7);  // = qv + 16384 - 128*hb  in [-64, 63]
        h[i]   = hb - 128;             // in [-128, 127]
    }
    hw = pack4b(h[0], h[1], h[2], h[3]);
    lw = pack4b(lo[0], lo[1], lo[2], lo[3]);
}

__device__ __forceinline__ void mma_s8(int c[4], const uint32_t a[4], const uint32_t b[2]) {
    asm volatile(
        "mma.sync.aligned.m16n8k32.row.col.s32.s8.s8.s32 "
        "{%0,%1,%2,%3}, {%4,%5,%6,%7}, {%8,%9}, {%0,%1,%2,%3};"
        : "+r"(c[0]), "+r"(c[1]), "+r"(c[2]), "+r"(c[3])
        : "r"(a[0]), "r"(a[1]), "r"(a[2]), "r"(a[3]), "r"(b[0]), "r"(b[1]));
}

__device__ __forceinline__ void cp16(uint32_t s, const void* g) {
    asm volatile("cp.async.cg.shared.global [%0], [%1], 16;" :: "r"(s), "l"(g));
}
__device__ __forceinline__ void cp_commit() { asm volatile("cp.async.commit_group;"); }
template <int W>
__device__ __forceinline__ void cp_wait() { asm volatile("cp.async.wait_group %0;" :: "n"(W)); }

// ---------------------------------------------------------------------------
// Kernel 1: psi GEMM.  C[fg, i] = sum_r w[fg, r] * D[r, i], scattered into g_W.
// grid = (8, 64)
// ---------------------------------------------------------------------------
__global__ void __launch_bounds__(256) build_w2_kernel(const float* __restrict__ D,
                                                       const float* __restrict__ w)
{
    const int dtab[7] = {1, 3, 5, 7, 9, 11, 13};
    const int otab[7] = {0, 1, 10, 35, 84, 165, 286};

    __shared__ float Wsh[64][68];
    __shared__ float Dsh[64][68];

    const int t   = threadIdx.x;
    const int fg0 = blockIdx.y * 64;
    const int i0  = blockIdx.x * 64;

    for (int idx = t; idx < 4096; idx += 256) {
        int row = idx >> 6, r = idx & 63;
        Wsh[r][row] = w[(fg0 + row) * 64 + r];
    }
    for (int idx = t; idx < 4096; idx += 256) {
        int r = idx >> 6, c = idx & 63;
        int i = i0 + c;
        Dsh[r][c] = (i < IR) ? D[r * IR + i] : 0.0f;
    }
    __syncthreads();

    const int ty = t >> 4, tx = t & 15;
    float acc[4][4] = {};

#pragma unroll 4
    for (int r = 0; r < 64; ++r) {
        float4 a4 = *(const float4*)&Wsh[r][ty * 4];
        float4 b4 = *(const float4*)&Dsh[r][tx * 4];
        float av[4] = {a4.x, a4.y, a4.z, a4.w};
        float bv[4] = {b4.x, b4.y, b4.z, b4.w};
#pragma unroll
        for (int i = 0; i < 4; ++i)
#pragma unroll
            for (int j = 0; j < 4; ++j)
                acc[i][j] += av[i] * bv[j];
    }

#pragma unroll
    for (int j = 0; j < 4; ++j) {
        const int i = i0 + tx * 4 + j;
        if (i >= IR) continue;
        int l = 0;
#pragma unroll
        for (int q = 1; q < 7; ++q)
            if (i >= otab[q]) l = q;
        const int d = dtab[l], off = otab[l];
        const int jj = i - off;
        const int u = jj / d, v = jj - u * d;
        const float scale = rsqrtf((float)d) * (1.0f / 64.0f);
        const int base = 4096 * off;
        const int N = 64 * d;
#pragma unroll
        for (int i4 = 0; i4 < 4; ++i4) {
            const int fg = fg0 + ty * 4 + i4;
            const int f = fg >> 6, gg = fg & 63;
            g_W[base + (f * d + u) * N + gg * d + v] = scale * acc[i4][j];
        }
    }
}

// ---------------------------------------------------------------------------
// Kernel 1b: per-column |max| -> quantization factor + epilogue scale.
// 3136 columns; coalesced over n. grid = 13 x 256.
// ---------------------------------------------------------------------------
__global__ void __launch_bounds__(256) colscale_kernel()
{
    const int dtab[7] = {1, 3, 5, 7, 9, 11, 13};
    const int otab[7] = {0, 1, 10, 35, 84, 165, 286};
    const int cb[8]   = {0, 64, 256, 576, 1024, 1600, 2304, 3136};

    const int c = blockIdx.x * 256 + threadIdx.x;
    if (c >= 3136) return;
    int l = 0;
#pragma unroll
    for (int q = 1; q < 7; ++q)
        if (c >= cb[q]) l = q;
    const int d = dtab[l], N = 64 * d, base = 4096 * otab[l];
    const int n = c - cb[l];

    float m = 0.0f;
    for (int k = 0; k < 64 * d; ++k)
        m = fmaxf(m, fabsf(g_W[base + k * N + n]));
    m = fmaxf(m, 1e-30f);

    g_qf[c]  = 16300.0f / m;
    g_epi[c] = m * (128.0f / (16300.0f * 2048.0f));
}

// ---------------------------------------------------------------------------
// Kernel 1c: quantize + pack W into fragment-ordered s8 limb planes.
// One thread per hi-word (writes hi and lo). grid = 1820 x 256 (465920 exact).
// ---------------------------------------------------------------------------
__global__ void __launch_bounds__(256) pack_q_kernel()
{
    const int dtab[7] = {1, 3, 5, 7, 9, 11, 13};
    const int otab[7] = {0, 1, 10, 35, 84, 165, 286};
    const int cb[7]   = {0, 64, 256, 576, 1024, 1600, 2304};

    const int tw = blockIdx.x * 256 + threadIdx.x;   // [0, 465920)
    int l = 0;
#pragma unroll
    for (int q = 1; q < 7; ++q)
        if (tw >= 1024 * otab[q]) l = q;
    const int d = dtab[l], N = 64 * d;
    const int local = tw - 1024 * otab[l];
    const int tile = local >> 9;        // (kc*d + bn)
    const int widx = local & 511;
    const int bn = tile % d;
    const int kc = tile / d;

    const int wt   = widx >> 8;
    const int rem  = widx & 255;
    const int half = rem >> 7;
    const int rem2 = rem & 127;
    const int lane = rem2 >> 2;
    const int j    = rem2 & 3;
    const int g    = lane >> 2, tg = lane & 3;
    const int ni   = half * 2 + (j >> 1);
    const int rg   = j & 1;

    const int n  = bn * 64 + wt * 32 + ni * 8 + g;
    const int kb = kc * 32 + tg * 4 + rg * 16;

    const float qf = g_qf[cb[l] + n];
    const float* Wp = g_W + 4096 * otab[l] + kb * N + n;

    int h[4], lo[4];
#pragma unroll
    for (int i = 0; i < 4; ++i) {
        int qv = __float2int_rn(Wp[i * N] * qf);   // |qv| <= 16301 by construction
        int tt = qv + 16448;
        int hb = tt >> 7;
        lo[i]  = tt - 64 - (hb << 7);
        h[i]   = hb - 128;
    }
    uint32_t* dst = g_Wq + 2048 * otab[l] + tile * 1024 + widx;
    dst[0]   = pack4b(h[0], h[1], h[2], h[3]);
    dst[512] = pack4b(lo[0], lo[1], lo[2], lo[3]);
}

// ---------------------------------------------------------------------------
// Kernel 2: fused GEMM, int8 2-limb Ozaki split, m16n8k32 IMMA.
// Block tile 128x64, 256 threads = 8 warps (4x2 of 32x32 warp tiles).
// K in 32-chunks; 24 IMMA per chunk; v9 pipeline (post-barrier A staging).
// ---------------------------------------------------------------------------
__global__ void __launch_bounds__(256, 2) so3_q_kernel(const float* __restrict__ x,
                                                       float* __restrict__ out)
{
    // ---- decode (l, bm, bn) ----
    int rem = blockIdx.x;
    int li = 0;
#pragma unroll
    for (int q = 0; q < 6; ++q)
        if (rem >= c_cnt[li]) { rem -= c_cnt[li]; li++; }
    const int d    = c_d[li];
    const int offl = c_off[li];
    const int colb = c_colb[li];
    const int bn   = rem % d;
    const int bm   = rem / d;

    __shared__ __align__(16) uint32_t A1F[2][1024];   // hi limb A frags
    __shared__ __align__(16) uint32_t A0F[2][1024];   // lo limb A frags
    __shared__ __align__(16) uint32_t BF [2][1024];   // [hi 512 | lo 512] per stage

    const int t    = threadIdx.x;
    const int wid  = t >> 5;
    const int lane = t & 31;
    const int g    = lane >> 2;
    const int tg   = lane & 3;
    const int wmi  = wid & 3;
    const int wt   = wid >> 2;

    // ---- A row bases (rows m, m+8 of this thread's fragment slot) ----
    const int m    = (t >> 5) * 16 + g;
    const int gr0  = bm * 128 + m;
    const int b0_  = gr0 / d;
    const int b8_  = (gr0 + 8) / d;
    const float* base0 = x + b0_ * FS + offl + (gr0 - b0_ * d);
    const float* base8 = x + b8_ * FS + offl + ((gr0 + 8) - b8_ * d);

    // ---- incremental k walk: one (u, off) pair; jumps +12 (creg) and +32 ----
    const int q12 = 12 / d, r12 = 12 - q12 * d;
    const int q32 = 32 / d, r32 = 32 - q32 * d;
    int u0, off0;
    { const int k0 = 4 * tg; const int f = k0 / d; u0 = k0 - f * d; off0 = f * IR + u0 * d; }

    // ---- B staging: one 4KB chunk per k32 tile ----
    const uint32_t* Wsrc = g_Wq + 2048 * offl + bn * 1024 + t * 4;
    const int WstepB = d * 1024;
    const uint32_t bf_b = (uint32_t)__cvta_generic_to_shared(&BF[0][0]);
    const uint32_t bsB  = bf_b + t * 16;

    int accH[2][4][4] = {};
    int accM[2][4][4] = {};
    uint32_t v[8];

#define LOAD_A() do {                                                        \
        int u = u0, off = off0;                                              \
        float r0[4], r8[4];                                                  \
        _Pragma("unroll")                                                    \
        for (int i = 0; i < 4; ++i) {                                        \
            r0[i] = base0[off]; r8[i] = base8[off];                          \
            off += d; if (++u == d) { u = 0; off += IR - d * d; }            \
        }                                                                    \
        quant4(r0, v[0], v[4]); quant4(r8, v[1], v[5]);                      \
        u += r12; off += q12 * IR + r12 * d;                                 \
        if (u >= d) { u -= d; off += IR - d * d; }                           \
        _Pragma("unroll")                                                    \
        for (int i = 0; i < 4; ++i) {                                        \
            r0[i] = base0[off]; r8[i] = base8[off];                          \
            off += d; if (++u == d) { u = 0; off += IR - d * d; }            \
        }                                                                    \
        quant4(r0, v[2], v[6]); quant4(r8, v[3], v[7]);                      \
        u0 += r32; off0 += q32 * IR + r32 * d;                               \
        if (u0 >= d) { u0 -= d; off0 += IR - d * d; }                        \
    } while (0)

#define STS_A(st) do {                                                       \
        *(uint4*)&A1F[st][t * 4] = make_uint4(v[0], v[1], v[2], v[3]);       \
        *(uint4*)&A0F[st][t * 4] = make_uint4(v[4], v[5], v[6], v[7]);       \
    } while (0)

    // ---- prologue ----
    LOAD_A();                 // A(0)
    STS_A(0);
    LOAD_A();                 // A(1) in regs
    cp16(bsB, Wsrc);          // B(0)
    cp_commit();
    Wsrc += WstepB;

    const int ntiles = 2 * d;  // k32 tiles
    for (int it = 0; it < ntiles; ++it) {
        const int s = it & 1;

        cp_wait<0>();
        __syncthreads();

        if (it + 1 < ntiles) {
            cp16(bsB + (s ^ 1) * 4096, Wsrc);
            cp_commit();
            Wsrc += WstepB;
        }

        // ---- 24 IMMA on stage s ----
        {
            uint32_t af[2][4], b1[4][2], b0r[4][2];
#pragma unroll
            for (int mi = 0; mi < 2; ++mi) {
                const int mt = wmi * 2 + mi;
                uint4 a4 = *(const uint4*)&A1F[s][(mt * 32 + lane) * 4];
                af[mi][0] = a4.x; af[mi][1] = a4.y; af[mi][2] = a4.z; af[mi][3] = a4.w;
            }
            {
                uint4 q0 = *(const uint4*)&BF[s][wt * 256 + lane * 4];
                uint4 q1 = *(const uint4*)&BF[s][wt * 256 + 128 + lane * 4];
                b1[0][0] = q0.x; b1[0][1] = q0.y; b1[1][0] = q0.z; b1[1][1] = q0.w;
                b1[2][0] = q1.x; b1[2][1] = q1.y; b1[3][0] = q1.z; b1[3][1] = q1.w;
            }
#pragma unroll
            for (int mi = 0; mi < 2; ++mi)
#pragma unroll
                for (int ni = 0; ni < 4; ++ni)
                    mma_s8(accH[mi][ni], af[mi], b1[ni]);     // a1*b1
            {
                uint4 q0 = *(const uint4*)&BF[s][512 + wt * 256 + lane * 4];
                uint4 q1 = *(const uint4*)&BF[s][512 + wt * 256 + 128 + lane * 4];
                b0r[0][0] = q0.x; b0r[0][1] = q0.y; b0r[1][0] = q0.z; b0r[1][1] = q0.w;
                b0r[2][0] = q1.x; b0r[2][1] = q1.y; b0r[3][0] = q1.z; b0r[3][1] = q1.w;
            }
#pragma unroll
            for (int mi = 0; mi < 2; ++mi)
#pragma unroll
                for (int ni = 0; ni < 4; ++ni)
                    mma_s8(accM[mi][ni], af[mi], b0r[ni]);    // a1*b0
#pragma unroll
            for (int mi = 0; mi < 2; ++mi) {
                const int mt = wmi * 2 + mi;
                uint4 a4 = *(const uint4*)&A0F[s][(mt * 32 + lane) * 4];
                af[mi][0] = a4.x; af[mi][1] = a4.y; af[mi][2] = a4.z; af[mi][3] = a4.w;
            }
#pragma unroll
            for (int mi = 0; mi < 2; ++mi)
#pragma unroll
                for (int ni = 0; ni < 4; ++ni)
                    mma_s8(accM[mi][ni], af[mi], b1[ni]);     // a0*b1
        }

        // ---- stage A(it+1) into s^1 (post-barrier, overlaps MMA issue) ----
        if (it + 1 < ntiles) {
            STS_A(s ^ 1);
            if (it + 2 < ntiles) LOAD_A();
        }
    }

#undef LOAD_A
#undef STS_A

    // ---- epilogue: y = es[n] * (128*accH + accM), scattered ----
    float es[8];
#pragma unroll
    for (int ni = 0; ni < 4; ++ni)
#pragma unroll
        for (int cc = 0; cc < 2; ++cc)
            es[ni * 2 + cc] = g_epi[colb + bn * 64 + wt * 32 + ni * 8 + tg * 2 + cc];

#pragma unroll
    for (int mi = 0; mi < 2; ++mi) {
#pragma unroll
        for (int cr = 0; cr < 2; ++cr) {
            const int row = bm * 128 + wmi * 32 + mi * 16 + g + cr * 8;
            const int b = row / d;
            const int mm = row - b * d;
            float* ob = out + b * FS + offl + mm;
#pragma unroll
            for (int ni = 0; ni < 4; ++ni) {
#pragma unroll
                for (int cc = 0; cc < 2; ++cc) {
                    const int col = bn * 64 + wt * 32 + ni * 8 + tg * 2 + cc;
                    const int gg = col / d;
                    const int vv = col - gg * d;
                    const float y = es[ni * 2 + cc] *
                        fmaf(128.0f, (float)accH[mi][ni][cr * 2 + cc],
                                     (float)accM[mi][ni][cr * 2 + cc]);
                    ob[gg * IR + vv * d] = y;
                }
            }
        }
    }
}

// ---------------------------------------------------------------------------
extern "C" void kernel_launch(void* const* d_in, const int* in_sizes, int n_in,
                              void* d_out, int out_size)
{
    const float* x = nullptr;
    const float* D = nullptr;
    const float* w = nullptr;
    for (int i = 0; i < n_in; ++i) {
        if (in_sizes[i] == NROT * IR)         D = (const float*)d_in[i];
        else if (in_sizes[i] == F * F * NROT) w = (const float*)d_in[i];
        else                                  x = (const float*)d_in[i];
    }
    float* out = (float*)d_out;

    build_w2_kernel<<<dim3(8, 64), 256>>>(D, w);
    colscale_kernel<<<13, 256>>>();
    pack_q_kernel<<<1820, 256>>>();      // 465920 / 256 exactly
    so3_q_kernel<<<3640, 256>>>(x, out);
}